// round 8
// baseline (speedup 1.0000x reference)
#include <cuda_runtime.h>
#include <math.h>

#define EPSF 1e-6f
#define LOG_BIAS 1.0f
#define MAXS 4096
#define MAXW 64
#define HP 16                  // padded head stride in segment table
#define MAXH 16
#define LUTN 4096
#define LN2F 0.69314718055994530942f

// Precomputed tables (device globals; zero-init, no allocation)
__device__ float  g_lr[MAXS];          // log_rel(d) (generic fallback only)
__device__ float  g_invln[MAXS];       // 1 / log_norm as function of row i
__device__ float  g_bp[MAXW + 1];      // sorted breakpoints (+inf padded)
__device__ __align__(16) float2 g_tab[(MAXW + 1) * HP];  // [seg][head] -> (slope, intercept)
__device__ unsigned char g_lut[LUTN];  // bit7: impure bin; low bits: segment
__device__ int   g_nbp;
__device__ float g_ndlo;
__device__ float g_scale;
__device__ float g_c, g_c1;            // c and (eps*c + 1 + eps)

// ---------------- unified setup: every block redundantly rank-sorts ------------
__global__ void __launch_bounds__(256)
fire_setup(const float* __restrict__ w1, const float* __restrict__ b1,
           const float* __restrict__ w2, const float* __restrict__ b2,
           const float* __restrict__ pc, const float* __restrict__ pLm,
           const float* __restrict__ pInit, int S, int W, int H) {
    __shared__ float sw1[MAXW], sb1[MAXW];
    __shared__ float s_raw_bp[MAXW];
    __shared__ float s_bp[MAXW + 1];    // sorted, +inf padded
    __shared__ int   s_sidx[MAXW];      // original weight index per sorted slot
    __shared__ float s_extra[MAXH];

    int t = threadIdx.x;
    int gid = blockIdx.x * blockDim.x + t;
    int gtot = gridDim.x * blockDim.x;
    const float INF = __int_as_float(0x7f800000);

    if (t < MAXW) {
        sw1[t] = (t < W) ? w1[t] : 0.0f;
        sb1[t] = (t < W) ? b1[t] : 0.0f;
    }
    float c   = *pc;
    float thr = fabsf((*pLm) * (*pInit));
    __syncthreads();

    // raw breakpoints (+inf for invalid / padded entries)
    if (t < MAXW) {
        float a = sw1[t];
        s_raw_bp[t] = (t < W && a != 0.0f) ? (-sb1[t] / a) : INF;
    }
    int valid = (t < W) && (t < MAXW) && (sw1[t] != 0.0f);
    int n = __syncthreads_count(valid);   // number of real breakpoints (also syncs)

    // parallel rank sort: thread e counts elements strictly before it
    if (t < MAXW) {
        float mybp = s_raw_bp[t];
        int rank = 0;
#pragma unroll
        for (int m = 0; m < MAXW; m++) {
            float o = s_raw_bp[m];
            rank += (o < mybp || (o == mybp && m < t)) ? 1 : 0;
        }
        s_bp[rank] = mybp;          // invalid (inf) entries land at the tail
        s_sidx[rank] = t;
    }
    if (t == 0) s_bp[MAXW] = INF;
    __syncthreads();

    // nd range from monotone endpoints; purity margin at use covers any
    // fast-log rounding differences at runtime.
    float l0 = logf(EPSF * c + LOG_BIAS + EPSF);
    float l1 = logf(((float)(S - 1) + EPSF) * c + LOG_BIAS + EPSF);
    float i0 = 1.0f / logf(fabsf(c * (fmaxf(0.0f, thr) + EPSF)) + LOG_BIAS + EPSF);
    float i1 = 1.0f / logf(fabsf(c * (fmaxf((float)(S - 1), thr) + EPSF)) + LOG_BIAS + EPSF);
    float p00 = l0 * i0, p01 = l0 * i1, p10 = l1 * i0, p11 = l1 * i1;
    float lo = fminf(fminf(p00, p01), fminf(p10, p11));
    float hi = fmaxf(fmaxf(p00, p01), fmaxf(p10, p11));
    float span = hi - lo;
    if (!(span > 0.0f)) span = 1.0f;
    // widen range slightly so fast-log runtime values stay inside bins 0..LUTN-1
    lo -= span * 2e-4f;
    float scale = (float)LUTN / (span * (1.0f + 4e-4f));

    // block 0 publishes scalars + sorted breakpoints for fire_main
    if (blockIdx.x == 0) {
        if (t == 0) {
            g_nbp = n; g_ndlo = lo; g_scale = scale;
            g_c = c; g_c1 = EPSF * c + LOG_BIAS + EPSF;
        }
        if (t <= MAXW) g_bp[t] = s_bp[t];
    }

    // log tables (grid-strided)
    for (int d = gid; d < S; d += gtot)
        g_lr[d] = logf(((float)d + EPSF) * c + LOG_BIAS + EPSF);
    for (int i = gid; i < S; i += gtot) {
        float pn = fmaxf((float)i, thr) + EPSF;
        g_invln[i] = 1.0f / logf(fabsf(c * pn) + LOG_BIAS + EPSF);
    }

    // segment tables (first blocks only)
    if (blockIdx.x * blockDim.x < (n + 1) * H) {
        if (t < H) {
            float e = 0.0f;
            for (int w = 0; w < W; w++)
                if (sw1[w] == 0.0f) e += w2[t * W + w] * fmaxf(sb1[w], 0.0f);
            s_extra[t] = e;
        }
        __syncthreads();
        // [seg][head] layout (stride HP). seg(nd) = #(sorted bp <= nd).
        // Sorted position p (weight w, a = w1[w]) is active in segment s
        //   <=>  (p < s) ? (a > 0) : (a < 0)
        for (int e = gid; e < (n + 1) * H; e += gtot) {
            int s = e / H, h = e % H;
            float slope = 0.0f;
            float inter = b2[h] + s_extra[h];
            for (int p = 0; p < n; p++) {
                int w = s_sidx[p];
                float a = sw1[w];
                bool act = (p < s) ? (a > 0.0f) : (a < 0.0f);
                if (act) {
                    float ww = w2[h * W + w];
                    slope += ww * a;
                    inter += ww * sb1[w];
                }
            }
            g_tab[s * HP + h] = make_float2(slope, inter);
        }
    }

    // purity-encoded quantized LUT. Bin k is pure iff no breakpoint lies in
    // [edge(k-1), edge(k+2)] (one-bin margin each side covers bin-index and
    // fast-log rounding). Pure -> byte = exact segment for ANY value mapping
    // to this bin. Impure -> 0x80 | seg-at-left-edge (refine start).
    for (int k = gid; k < LUTN; k += gtot) {
        float edgeL = lo + (float)(k - 1) / scale;
        float edgeR = lo + (float)(k + 2) / scale;
        float edgeO = lo + (float)k / scale;
        int cL = 0, cR = 0, cO = 0;
        for (int p = 0; p < n; p++) {
            float b = s_bp[p];
            cL += (b <= edgeL);
            cR += (b <= edgeR);
            cO += (b <= edgeO);
        }
        g_lut[k] = (cL == cR) ? (unsigned char)cL : (unsigned char)(0x80 | cO);
    }
}

// ---------------- main kernel --------------------------------------------------
#define ROWS_PER_BLOCK 4

template <int H>
__global__ void __launch_bounds__(256, 5)
fire_main(float* __restrict__ out, int S) {
    __shared__ unsigned int  s_lut[LUTN / 4];
    __shared__ float         s_bp[MAXW + 1];
    __shared__ __align__(16) float2 s_tab[(MAXW + 1) * HP];

    int t = threadIdx.x;
    const int nbp = g_nbp;
    const unsigned int* glut = reinterpret_cast<const unsigned int*>(g_lut);
    for (int k = t; k < LUTN / 4; k += blockDim.x)   s_lut[k] = glut[k];
    if (t <= MAXW)                                   s_bp[t] = g_bp[t];
    for (int k = t; k < (nbp + 1) * HP; k += blockDim.x) s_tab[k] = g_tab[k];
    __syncthreads();
    const unsigned char* s_lut8 = reinterpret_cast<const unsigned char*>(s_lut);

    const float ndlo  = g_ndlo;
    const float scale = g_scale;
    const float c     = g_c;
    const float c1    = g_c1;
    const size_t SS   = (size_t)S * (size_t)S;

    for (int r = 0; r < ROWS_PER_BLOCK; r++) {
        int i = blockIdx.x * ROWS_PER_BLOCK + r;
        if (i >= S) return;
        const float invc = g_invln[i] * LN2F;   // fold ln2 of log2 -> ln

        // 8 columns per thread per iteration (two float4 groups)
        for (int j0 = t * 8; j0 + 7 < S; j0 += blockDim.x * 8) {
            float nd[8];
            unsigned int b[8];
#pragma unroll
            for (int k = 0; k < 8; k++) {
                int d = abs(i - (j0 + k));
                float v = __log2f(fmaf((float)d, c, c1)) * invc;
                nd[k] = v;
                int kq = (int)((v - ndlo) * scale);
                kq = max(0, min(LUTN - 1, kq));
                b[k] = s_lut8[kq];
            }
            float* a = out + (size_t)i * S + j0;
            unsigned int beq = b[0];
            bool all8 = true;
#pragma unroll
            for (int k = 1; k < 8; k++) all8 &= (b[k] == beq);
            if (all8 && !(beq & 0x80u)) {
                // pure uniform 8-wide: one set of table loads, 24 STG.128
                const float4* tp = reinterpret_cast<const float4*>(s_tab + (int)beq * HP);
#pragma unroll
                for (int hh = 0; hh < H / 2; hh++) {
                    float4 p = tp[hh];     // head 2hh: (x,y); head 2hh+1: (z,w)
                    float4 o;
                    float* a0 = a + (size_t)(2 * hh) * SS;
                    float* a1 = a + (size_t)(2 * hh + 1) * SS;
                    o.x = fmaf(nd[0], p.x, p.y); o.y = fmaf(nd[1], p.x, p.y);
                    o.z = fmaf(nd[2], p.x, p.y); o.w = fmaf(nd[3], p.x, p.y);
                    *reinterpret_cast<float4*>(a0) = o;
                    o.x = fmaf(nd[4], p.x, p.y); o.y = fmaf(nd[5], p.x, p.y);
                    o.z = fmaf(nd[6], p.x, p.y); o.w = fmaf(nd[7], p.x, p.y);
                    *reinterpret_cast<float4*>(a0 + 4) = o;
                    o.x = fmaf(nd[0], p.z, p.w); o.y = fmaf(nd[1], p.z, p.w);
                    o.z = fmaf(nd[2], p.z, p.w); o.w = fmaf(nd[3], p.z, p.w);
                    *reinterpret_cast<float4*>(a1) = o;
                    o.x = fmaf(nd[4], p.z, p.w); o.y = fmaf(nd[5], p.z, p.w);
                    o.z = fmaf(nd[6], p.z, p.w); o.w = fmaf(nd[7], p.z, p.w);
                    *reinterpret_cast<float4*>(a1 + 4) = o;
                }
                if (H & 1) {
                    float2 p = s_tab[(int)beq * HP + (H - 1)];
                    float* ah = a + (size_t)(H - 1) * SS;
                    float4 o;
                    o.x = fmaf(nd[0], p.x, p.y); o.y = fmaf(nd[1], p.x, p.y);
                    o.z = fmaf(nd[2], p.x, p.y); o.w = fmaf(nd[3], p.x, p.y);
                    *reinterpret_cast<float4*>(ah) = o;
                    o.x = fmaf(nd[4], p.x, p.y); o.y = fmaf(nd[5], p.x, p.y);
                    o.z = fmaf(nd[6], p.x, p.y); o.w = fmaf(nd[7], p.x, p.y);
                    *reinterpret_cast<float4*>(ah + 4) = o;
                }
            } else {
                // rare: segment transition or impure bin -> exact refine per col
#pragma unroll
                for (int g = 0; g < 2; g++) {
                    int sg[4];
#pragma unroll
                    for (int k = 0; k < 4; k++) {
                        int kk = g * 4 + k;
                        int s = (int)(b[kk] & 0x7fu);
                        float v = nd[kk];
                        while (s > 0 && v < s_bp[s - 1]) s--;
                        while (s < nbp && v >= s_bp[s]) s++;
                        sg[k] = s;
                    }
                    const float* ndg = nd + g * 4;
                    float* ag = a + g * 4;
#pragma unroll 4
                    for (int h = 0; h < H; h++) {
                        float2 t0 = s_tab[sg[0] * HP + h];
                        float2 t1 = s_tab[sg[1] * HP + h];
                        float2 t2 = s_tab[sg[2] * HP + h];
                        float2 t3 = s_tab[sg[3] * HP + h];
                        float4 o;
                        o.x = fmaf(ndg[0], t0.x, t0.y);
                        o.y = fmaf(ndg[1], t1.x, t1.y);
                        o.z = fmaf(ndg[2], t2.x, t2.y);
                        o.w = fmaf(ndg[3], t3.x, t3.y);
                        *reinterpret_cast<float4*>(ag + (size_t)h * SS) = o;
                    }
                }
            }
        }

        // scalar tail (only if S % 8 != 0)
        int tail = S & ~7;
        for (int j = tail + t; j < S; j += blockDim.x) {
            int d = abs(i - j);
            float v = __log2f(fmaf((float)d, c, c1)) * invc;
            int kq = (int)((v - ndlo) * scale);
            kq = max(0, min(LUTN - 1, kq));
            int s = (int)(s_lut8[kq] & 0x7fu);
            while (s > 0 && v < s_bp[s - 1]) s--;
            while (s < nbp && v >= s_bp[s]) s++;
            for (int h = 0; h < H; h++) {
                float2 ti = s_tab[s * HP + h];
                out[(size_t)h * SS + (size_t)i * S + j] = fmaf(v, ti.x, ti.y);
            }
        }
    }
}

// generic-H fallback (same algorithm, runtime H)
__global__ void __launch_bounds__(256)
fire_main_gen(float* __restrict__ out, int S, int H) {
    int t = threadIdx.x;
    const int   nbp   = g_nbp;
    const float ndlo  = g_ndlo;
    const float scale = g_scale;
    const size_t SS   = (size_t)S * (size_t)S;

    for (int r = 0; r < ROWS_PER_BLOCK; r++) {
        int i = blockIdx.x * ROWS_PER_BLOCK + r;
        if (i >= S) return;
        const float invln = __ldg(&g_invln[i]);
        for (int j = t; j < S; j += blockDim.x) {
            int d = abs(i - j);
            float v = __ldg(&g_lr[d]) * invln;
            int kq = (int)((v - ndlo) * scale);
            kq = max(0, min(LUTN - 1, kq));
            int s = (int)(__ldg(&g_lut[kq]) & 0x7fu);
            while (s > 0 && v < __ldg(&g_bp[s - 1])) s--;
            while (s < nbp && v >= __ldg(&g_bp[s])) s++;
            for (int h = 0; h < H; h++) {
                float2 ti = __ldg(&g_tab[s * HP + h]);
                out[(size_t)h * SS + (size_t)i * S + j] = fmaf(v, ti.x, ti.y);
            }
        }
    }
}

extern "C" void kernel_launch(void* const* d_in, const int* in_sizes, int n_in,
                              void* d_out, int out_size) {
    // metadata order: x, w1, b1, w2, b2, c, L_multiplier, init_L
    const float* w1 = (const float*)d_in[1];
    const float* b1 = (const float*)d_in[2];
    const float* w2 = (const float*)d_in[3];
    const float* b2 = (const float*)d_in[4];
    const float* c  = (const float*)d_in[5];
    const float* Lm = (const float*)d_in[6];
    const float* iL = (const float*)d_in[7];

    int W = in_sizes[2];
    int H = in_sizes[4];
    long long SSll = (long long)out_size / (long long)H;
    int S = (int)(sqrt((double)SSll) + 0.5);

    fire_setup<<<64, 256>>>(w1, b1, w2, b2, c, Lm, iL, S, W, H);

    dim3 grid((S + ROWS_PER_BLOCK - 1) / ROWS_PER_BLOCK);
    if (H == 12)
        fire_main<12><<<grid, 256>>>((float*)d_out, S);
    else
        fire_main_gen<<<grid, 256>>>((float*)d_out, S, H);
}

// round 10
// speedup vs baseline: 1.2800x; 1.2800x over previous
#include <cuda_runtime.h>
#include <math.h>

#define EPSF 1e-6f
#define LOG_BIAS 1.0f
#define MAXS 4096
#define MAXW 64
#define HP 16                  // padded head stride in segment table
#define MAXH 16
#define LUTN 4096
#define LN2F 0.69314718055994530942f

// Precomputed tables (device globals; zero-init, no allocation)
__device__ float  g_lr[MAXS];          // log_rel(d) (generic fallback only)
__device__ float  g_invln[MAXS];       // 1 / log_norm as function of row i
__device__ float  g_bp[MAXW + 1];      // sorted breakpoints (+inf padded)
__device__ __align__(16) float2 g_tab[(MAXW + 1) * HP];  // [seg][head] -> (slope, intercept)
__device__ unsigned char g_lut[LUTN];  // bit7: impure bin; low bits: segment
__device__ int   g_nbp;
__device__ float g_ndlo;
__device__ float g_scale;
__device__ float g_c, g_c1;            // c and (eps*c + 1 + eps)

// ---------------- unified setup: every block redundantly rank-sorts ------------
__global__ void __launch_bounds__(256)
fire_setup(const float* __restrict__ w1, const float* __restrict__ b1,
           const float* __restrict__ w2, const float* __restrict__ b2,
           const float* __restrict__ pc, const float* __restrict__ pLm,
           const float* __restrict__ pInit, int S, int W, int H) {
    __shared__ float sw1[MAXW], sb1[MAXW];
    __shared__ float s_raw_bp[MAXW];
    __shared__ float s_bp[MAXW + 1];    // sorted, +inf padded
    __shared__ int   s_sidx[MAXW];      // original weight index per sorted slot
    __shared__ float s_extra[MAXH];

    int t = threadIdx.x;
    int gid = blockIdx.x * blockDim.x + t;
    int gtot = gridDim.x * blockDim.x;
    const float INF = __int_as_float(0x7f800000);

    if (t < MAXW) {
        sw1[t] = (t < W) ? w1[t] : 0.0f;
        sb1[t] = (t < W) ? b1[t] : 0.0f;
    }
    float c   = *pc;
    float thr = fabsf((*pLm) * (*pInit));
    __syncthreads();

    // raw breakpoints (+inf for invalid / padded entries)
    if (t < MAXW) {
        float a = sw1[t];
        s_raw_bp[t] = (t < W && a != 0.0f) ? (-sb1[t] / a) : INF;
    }
    int valid = (t < W) && (t < MAXW) && (sw1[t] != 0.0f);
    int n = __syncthreads_count(valid);   // number of real breakpoints (also syncs)

    // parallel rank sort: thread e counts elements strictly before it
    if (t < MAXW) {
        float mybp = s_raw_bp[t];
        int rank = 0;
#pragma unroll
        for (int m = 0; m < MAXW; m++) {
            float o = s_raw_bp[m];
            rank += (o < mybp || (o == mybp && m < t)) ? 1 : 0;
        }
        s_bp[rank] = mybp;          // invalid (inf) entries land at the tail
        s_sidx[rank] = t;
    }
    if (t == 0) s_bp[MAXW] = INF;
    __syncthreads();

    // nd range from monotone endpoints; purity margin at use covers any
    // fast-log rounding differences at runtime.
    float l0 = logf(EPSF * c + LOG_BIAS + EPSF);
    float l1 = logf(((float)(S - 1) + EPSF) * c + LOG_BIAS + EPSF);
    float i0 = 1.0f / logf(fabsf(c * (fmaxf(0.0f, thr) + EPSF)) + LOG_BIAS + EPSF);
    float i1 = 1.0f / logf(fabsf(c * (fmaxf((float)(S - 1), thr) + EPSF)) + LOG_BIAS + EPSF);
    float p00 = l0 * i0, p01 = l0 * i1, p10 = l1 * i0, p11 = l1 * i1;
    float lo = fminf(fminf(p00, p01), fminf(p10, p11));
    float hi = fmaxf(fmaxf(p00, p01), fmaxf(p10, p11));
    float span = hi - lo;
    if (!(span > 0.0f)) span = 1.0f;
    // widen range slightly so fast-log runtime values stay inside bins 0..LUTN-1
    lo -= span * 2e-4f;
    float scale = (float)LUTN / (span * (1.0f + 4e-4f));

    // block 0 publishes scalars + sorted breakpoints for fire_main
    if (blockIdx.x == 0) {
        if (t == 0) {
            g_nbp = n; g_ndlo = lo; g_scale = scale;
            g_c = c; g_c1 = EPSF * c + LOG_BIAS + EPSF;
        }
        if (t <= MAXW) g_bp[t] = s_bp[t];
    }

    // log tables (grid-strided)
    for (int d = gid; d < S; d += gtot)
        g_lr[d] = logf(((float)d + EPSF) * c + LOG_BIAS + EPSF);
    for (int i = gid; i < S; i += gtot) {
        float pn = fmaxf((float)i, thr) + EPSF;
        g_invln[i] = 1.0f / logf(fabsf(c * pn) + LOG_BIAS + EPSF);
    }

    // segment tables (first blocks only)
    if (blockIdx.x * blockDim.x < (n + 1) * H) {
        if (t < H) {
            float e = 0.0f;
            for (int w = 0; w < W; w++)
                if (sw1[w] == 0.0f) e += w2[t * W + w] * fmaxf(sb1[w], 0.0f);
            s_extra[t] = e;
        }
        __syncthreads();
        // [seg][head] layout (stride HP). seg(nd) = #(sorted bp <= nd).
        // Sorted position p (weight w, a = w1[w]) is active in segment s
        //   <=>  (p < s) ? (a > 0) : (a < 0)
        for (int e = gid; e < (n + 1) * H; e += gtot) {
            int s = e / H, h = e % H;
            float slope = 0.0f;
            float inter = b2[h] + s_extra[h];
            for (int p = 0; p < n; p++) {
                int w = s_sidx[p];
                float a = sw1[w];
                bool act = (p < s) ? (a > 0.0f) : (a < 0.0f);
                if (act) {
                    float ww = w2[h * W + w];
                    slope += ww * a;
                    inter += ww * sb1[w];
                }
            }
            g_tab[s * HP + h] = make_float2(slope, inter);
        }
    }

    // purity-encoded quantized LUT. Bin k is pure iff no breakpoint lies in
    // [edge(k-1), edge(k+2)] (one-bin margin each side covers bin-index and
    // fast-log rounding). Pure -> byte = exact segment for ANY value mapping
    // to this bin. Impure -> 0x80 | seg-at-left-edge (refine start).
    for (int k = gid; k < LUTN; k += gtot) {
        float edgeL = lo + (float)(k - 1) / scale;
        float edgeR = lo + (float)(k + 2) / scale;
        float edgeO = lo + (float)k / scale;
        int cL = 0, cR = 0, cO = 0;
        for (int p = 0; p < n; p++) {
            float b = s_bp[p];
            cL += (b <= edgeL);
            cR += (b <= edgeR);
            cO += (b <= edgeO);
        }
        g_lut[k] = (cL == cR) ? (unsigned char)cL : (unsigned char)(0x80 | cO);
    }
}

// ---------------- main kernel --------------------------------------------------
#define ROWS_PER_BLOCK 4

template <int H>
__global__ void __launch_bounds__(256, 5)
fire_main(float* __restrict__ out, int S) {
    __shared__ unsigned int  s_lut[LUTN / 4];
    __shared__ float         s_bp[MAXW + 1];
    __shared__ __align__(16) float2 s_tab[(MAXW + 1) * HP];

    int t = threadIdx.x;
    const int nbp = g_nbp;
    const unsigned int* glut = reinterpret_cast<const unsigned int*>(g_lut);
    for (int k = t; k < LUTN / 4; k += blockDim.x)   s_lut[k] = glut[k];
    if (t <= MAXW)                                   s_bp[t] = g_bp[t];
    for (int k = t; k < (nbp + 1) * HP; k += blockDim.x) s_tab[k] = g_tab[k];
    __syncthreads();
    const unsigned char* s_lut8 = reinterpret_cast<const unsigned char*>(s_lut);

    const float ndlo  = g_ndlo;
    const float scale = g_scale;
    const float c     = g_c;
    const float c1    = g_c1;
    const size_t SS   = (size_t)S * (size_t)S;

    for (int r = 0; r < ROWS_PER_BLOCK; r++) {
        int i = blockIdx.x * ROWS_PER_BLOCK + r;
        if (i >= S) return;
        const float invc = g_invln[i] * LN2F;   // fold ln2 of log2 -> ln

        // 4 consecutive columns per thread: warp stores are dense 2KB bursts
        for (int j0 = t * 4; j0 + 3 < S; j0 += blockDim.x * 4) {
            float nd[4];
            unsigned int b[4];
#pragma unroll
            for (int k = 0; k < 4; k++) {
                int d = abs(i - (j0 + k));
                float v = __log2f(fmaf((float)d, c, c1)) * invc;
                nd[k] = v;
                int kq = (int)((v - ndlo) * scale);
                kq = max(0, min(LUTN - 1, kq));
                b[k] = s_lut8[kq];
            }
            float* a = out + (size_t)i * S + j0;
            if (b[0] == b[1] && b[1] == b[2] && b[2] == b[3] && !(b[0] & 0x80u)) {
                // pure uniform bin: segment known, no s_bp access
                const float4* tp = reinterpret_cast<const float4*>(s_tab + (int)b[0] * HP);
#pragma unroll
                for (int hh = 0; hh < H / 2; hh++) {
                    float4 p = tp[hh];     // head 2hh: (x,y); head 2hh+1: (z,w)
                    float4 o0, o1;
                    o0.x = fmaf(nd[0], p.x, p.y);
                    o0.y = fmaf(nd[1], p.x, p.y);
                    o0.z = fmaf(nd[2], p.x, p.y);
                    o0.w = fmaf(nd[3], p.x, p.y);
                    o1.x = fmaf(nd[0], p.z, p.w);
                    o1.y = fmaf(nd[1], p.z, p.w);
                    o1.z = fmaf(nd[2], p.z, p.w);
                    o1.w = fmaf(nd[3], p.z, p.w);
                    *reinterpret_cast<float4*>(a + (size_t)(2 * hh)     * SS) = o0;
                    *reinterpret_cast<float4*>(a + (size_t)(2 * hh + 1) * SS) = o1;
                }
                if (H & 1) {
                    float2 p = s_tab[(int)b[0] * HP + (H - 1)];
                    float4 o;
                    o.x = fmaf(nd[0], p.x, p.y);
                    o.y = fmaf(nd[1], p.x, p.y);
                    o.z = fmaf(nd[2], p.x, p.y);
                    o.w = fmaf(nd[3], p.x, p.y);
                    *reinterpret_cast<float4*>(a + (size_t)(H - 1) * SS) = o;
                }
            } else {
                // rare: impure bin or segment transition -> exact refine per col
                int sg[4];
#pragma unroll
                for (int k = 0; k < 4; k++) {
                    int s = (int)(b[k] & 0x7fu);
                    float v = nd[k];
                    while (s > 0 && v < s_bp[s - 1]) s--;
                    while (s < nbp && v >= s_bp[s]) s++;
                    sg[k] = s;
                }
#pragma unroll 4
                for (int h = 0; h < H; h++) {
                    float2 t0 = s_tab[sg[0] * HP + h];
                    float2 t1 = s_tab[sg[1] * HP + h];
                    float2 t2 = s_tab[sg[2] * HP + h];
                    float2 t3 = s_tab[sg[3] * HP + h];
                    float4 o;
                    o.x = fmaf(nd[0], t0.x, t0.y);
                    o.y = fmaf(nd[1], t1.x, t1.y);
                    o.z = fmaf(nd[2], t2.x, t2.y);
                    o.w = fmaf(nd[3], t3.x, t3.y);
                    *reinterpret_cast<float4*>(a + (size_t)h * SS) = o;
                }
            }
        }

        // scalar tail (only if S % 4 != 0)
        int tail = S & ~3;
        for (int j = tail + t; j < S; j += blockDim.x) {
            int d = abs(i - j);
            float v = __log2f(fmaf((float)d, c, c1)) * invc;
            int kq = (int)((v - ndlo) * scale);
            kq = max(0, min(LUTN - 1, kq));
            int s = (int)(s_lut8[kq] & 0x7fu);
            while (s > 0 && v < s_bp[s - 1]) s--;
            while (s < nbp && v >= s_bp[s]) s++;
            for (int h = 0; h < H; h++) {
                float2 ti = s_tab[s * HP + h];
                out[(size_t)h * SS + (size_t)i * S + j] = fmaf(v, ti.x, ti.y);
            }
        }
    }
}

// generic-H fallback (same algorithm, runtime H)
__global__ void __launch_bounds__(256)
fire_main_gen(float* __restrict__ out, int S, int H) {
    int t = threadIdx.x;
    const int   nbp   = g_nbp;
    const float ndlo  = g_ndlo;
    const float scale = g_scale;
    const size_t SS   = (size_t)S * (size_t)S;

    for (int r = 0; r < ROWS_PER_BLOCK; r++) {
        int i = blockIdx.x * ROWS_PER_BLOCK + r;
        if (i >= S) return;
        const float invln = __ldg(&g_invln[i]);
        for (int j = t; j < S; j += blockDim.x) {
            int d = abs(i - j);
            float v = __ldg(&g_lr[d]) * invln;
            int kq = (int)((v - ndlo) * scale);
            kq = max(0, min(LUTN - 1, kq));
            int s = (int)(__ldg(&g_lut[kq]) & 0x7fu);
            while (s > 0 && v < __ldg(&g_bp[s - 1])) s--;
            while (s < nbp && v >= __ldg(&g_bp[s])) s++;
            for (int h = 0; h < H; h++) {
                float2 ti = __ldg(&g_tab[s * HP + h]);
                out[(size_t)h * SS + (size_t)i * S + j] = fmaf(v, ti.x, ti.y);
            }
        }
    }
}

extern "C" void kernel_launch(void* const* d_in, const int* in_sizes, int n_in,
                              void* d_out, int out_size) {
    // metadata order: x, w1, b1, w2, b2, c, L_multiplier, init_L
    const float* w1 = (const float*)d_in[1];
    const float* b1 = (const float*)d_in[2];
    const float* w2 = (const float*)d_in[3];
    const float* b2 = (const float*)d_in[4];
    const float* c  = (const float*)d_in[5];
    const float* Lm = (const float*)d_in[6];
    const float* iL = (const float*)d_in[7];

    int W = in_sizes[2];
    int H = in_sizes[4];
    long long SSll = (long long)out_size / (long long)H;
    int S = (int)(sqrt((double)SSll) + 0.5);

    fire_setup<<<64, 256>>>(w1, b1, w2, b2, c, Lm, iL, S, W, H);

    dim3 grid((S + ROWS_PER_BLOCK - 1) / ROWS_PER_BLOCK);
    if (H == 12)
        fire_main<12><<<grid, 256>>>((float*)d_out, S);
    else
        fire_main_gen<<<grid, 256>>>((float*)d_out, S, H);
}

// round 12
// speedup vs baseline: 1.3604x; 1.0628x over previous
#include <cuda_runtime.h>
#include <math.h>

#define EPSF 1e-6f
#define LOG_BIAS 1.0f
#define MAXS 4096
#define MAXW 64
#define HP 16                  // padded head stride in segment table
#define MAXH 16
#define LUTN 4096

// Precomputed tables (device globals; zero-init, no allocation)
__device__ float  g_lr[MAXS];          // log_rel as function of d = |i-j|
__device__ float  g_invln[MAXS];       // 1 / log_norm as function of row i
__device__ float  g_bp[MAXW + 1];      // sorted breakpoints (+inf padded)
__device__ __align__(16) float2 g_tab[(MAXW + 1) * HP];  // [seg][head] -> (slope, intercept)
__device__ unsigned char g_lut[LUTN];  // bit7: impure bin; low bits: segment
__device__ int   g_nbp;
__device__ float g_ndlo;
__device__ float g_scale;

// ---------------- unified setup: every block redundantly rank-sorts ------------
__global__ void __launch_bounds__(256)
fire_setup(const float* __restrict__ w1, const float* __restrict__ b1,
           const float* __restrict__ w2, const float* __restrict__ b2,
           const float* __restrict__ pc, const float* __restrict__ pLm,
           const float* __restrict__ pInit, int S, int W, int H) {
    __shared__ float sw1[MAXW], sb1[MAXW];
    __shared__ float s_raw_bp[MAXW];
    __shared__ float s_bp[MAXW + 1];    // sorted, +inf padded
    __shared__ int   s_sidx[MAXW];      // original weight index per sorted slot
    __shared__ float s_extra[MAXH];

    int t = threadIdx.x;
    int gid = blockIdx.x * blockDim.x + t;
    int gtot = gridDim.x * blockDim.x;
    const float INF = __int_as_float(0x7f800000);

    if (t < MAXW) {
        sw1[t] = (t < W) ? w1[t] : 0.0f;
        sb1[t] = (t < W) ? b1[t] : 0.0f;
    }
    float c   = *pc;
    float thr = fabsf((*pLm) * (*pInit));
    __syncthreads();

    // raw breakpoints (+inf for invalid / padded entries)
    if (t < MAXW) {
        float a = sw1[t];
        s_raw_bp[t] = (t < W && a != 0.0f) ? (-sb1[t] / a) : INF;
    }
    int valid = (t < W) && (t < MAXW) && (sw1[t] != 0.0f);
    int n = __syncthreads_count(valid);   // number of real breakpoints (also syncs)

    // parallel rank sort: thread e counts elements strictly before it
    if (t < MAXW) {
        float mybp = s_raw_bp[t];
        int rank = 0;
#pragma unroll
        for (int m = 0; m < MAXW; m++) {
            float o = s_raw_bp[m];
            rank += (o < mybp || (o == mybp && m < t)) ? 1 : 0;
        }
        s_bp[rank] = mybp;          // invalid (inf) entries land at the tail
        s_sidx[rank] = t;
    }
    if (t == 0) s_bp[MAXW] = INF;
    __syncthreads();

    // nd range from monotone endpoints (LUT binning only; refine makes it exact)
    float l0 = logf(EPSF * c + LOG_BIAS + EPSF);
    float l1 = logf(((float)(S - 1) + EPSF) * c + LOG_BIAS + EPSF);
    float i0 = 1.0f / logf(fabsf(c * (fmaxf(0.0f, thr) + EPSF)) + LOG_BIAS + EPSF);
    float i1 = 1.0f / logf(fabsf(c * (fmaxf((float)(S - 1), thr) + EPSF)) + LOG_BIAS + EPSF);
    float p00 = l0 * i0, p01 = l0 * i1, p10 = l1 * i0, p11 = l1 * i1;
    float lo = fminf(fminf(p00, p01), fminf(p10, p11));
    float hi = fmaxf(fmaxf(p00, p01), fmaxf(p10, p11));
    float span = hi - lo;
    if (!(span > 0.0f)) span = 1.0f;
    lo -= span * 2e-4f;
    float scale = (float)LUTN / (span * (1.0f + 4e-4f));

    // block 0 publishes scalars + sorted breakpoints for fire_main
    if (blockIdx.x == 0) {
        if (t == 0) { g_nbp = n; g_ndlo = lo; g_scale = scale; }
        if (t <= MAXW) g_bp[t] = s_bp[t];
    }

    // log tables (grid-strided)
    for (int d = gid; d < S; d += gtot)
        g_lr[d] = logf(((float)d + EPSF) * c + LOG_BIAS + EPSF);
    for (int i = gid; i < S; i += gtot) {
        float pn = fmaxf((float)i, thr) + EPSF;
        g_invln[i] = 1.0f / logf(fabsf(c * pn) + LOG_BIAS + EPSF);
    }

    // segment tables (first blocks only)
    if (blockIdx.x * blockDim.x < (n + 1) * H) {
        if (t < H) {
            float e = 0.0f;
            for (int w = 0; w < W; w++)
                if (sw1[w] == 0.0f) e += w2[t * W + w] * fmaxf(sb1[w], 0.0f);
            s_extra[t] = e;
        }
        __syncthreads();
        // [seg][head] layout (stride HP). seg(nd) = #(sorted bp <= nd).
        // Sorted position p (weight w, a = w1[w]) is active in segment s
        //   <=>  (p < s) ? (a > 0) : (a < 0)
        for (int e = gid; e < (n + 1) * H; e += gtot) {
            int s = e / H, h = e % H;
            float slope = 0.0f;
            float inter = b2[h] + s_extra[h];
            for (int p = 0; p < n; p++) {
                int w = s_sidx[p];
                float a = sw1[w];
                bool act = (p < s) ? (a > 0.0f) : (a < 0.0f);
                if (act) {
                    float ww = w2[h * W + w];
                    slope += ww * a;
                    inter += ww * sb1[w];
                }
            }
            g_tab[s * HP + h] = make_float2(slope, inter);
        }
    }

    // purity-encoded quantized LUT. Bin k is pure iff no breakpoint lies in
    // [edge(k-1), edge(k+2)] (one-bin safety margin each side). Pure -> byte =
    // exact segment for ANY value mapping to this bin. Impure -> 0x80 | seg.
    for (int k = gid; k < LUTN; k += gtot) {
        float edgeL = lo + (float)(k - 1) / scale;
        float edgeR = lo + (float)(k + 2) / scale;
        float edgeO = lo + (float)k / scale;
        int cL = 0, cR = 0, cO = 0;
        for (int p = 0; p < n; p++) {
            float b = s_bp[p];
            cL += (b <= edgeL);
            cR += (b <= edgeR);
            cO += (b <= edgeO);
        }
        g_lut[k] = (cL == cR) ? (unsigned char)cL : (unsigned char)(0x80 | cO);
    }
}

// ---------------- main kernel: per-row seg-of-distance table, branch-free sweep -
#define ROWS_PER_BLOCK 4

template <int H>
__global__ void __launch_bounds__(256, 4)
fire_main(float* __restrict__ out, int S) {
    __shared__ float         s_lr[MAXS];
    __shared__ unsigned int  s_lut[LUTN / 4];
    __shared__ float         s_bp[MAXW + 1];
    __shared__ __align__(16) float2 s_tab[(MAXW + 1) * HP];
    __shared__ unsigned char s_segd[MAXS];   // per-row: segment as function of d

    int t = threadIdx.x;
    const int nbp = g_nbp;
    for (int d = t; d < S; d += blockDim.x)          s_lr[d] = g_lr[d];
    const unsigned int* glut = reinterpret_cast<const unsigned int*>(g_lut);
    for (int k = t; k < LUTN / 4; k += blockDim.x)   s_lut[k] = glut[k];
    if (t <= MAXW)                                   s_bp[t] = g_bp[t];
    for (int k = t; k < (nbp + 1) * HP; k += blockDim.x) s_tab[k] = g_tab[k];
    __syncthreads();
    const unsigned char* s_lut8 = reinterpret_cast<const unsigned char*>(s_lut);
    const float4* tab4 = reinterpret_cast<const float4*>(s_tab);

    const float ndlo  = g_ndlo;
    const float scale = g_scale;
    const size_t SS   = (size_t)S * (size_t)S;

    for (int r = 0; r < ROWS_PER_BLOCK; r++) {
        int i = blockIdx.x * ROWS_PER_BLOCK + r;
        if (i >= S) break;                      // block-uniform
        const float invln = g_invln[i];

        // Phase A: build segment-per-distance table for this row (amortized:
        // S entries vs S*H outputs). Refine only on impure bins.
        for (int d = t; d < S; d += blockDim.x) {
            float v = s_lr[d] * invln;
            int kq = (int)((v - ndlo) * scale);
            kq = max(0, min(LUTN - 1, kq));
            unsigned int b = s_lut8[kq];
            int s = (int)(b & 0x7fu);
            if (b & 0x80u) {
                while (s > 0 && v < s_bp[s - 1]) s--;
                while (s < nbp && v >= s_bp[s]) s++;
            }
            s_segd[d] = (unsigned char)s;
        }
        __syncthreads();

        // Phase B: branch-free sweep. 4 consecutive cols/thread (dense stores).
        for (int j0 = t * 4; j0 + 3 < S; j0 += blockDim.x * 4) {
            float v[4];
            int   sg[4];
#pragma unroll
            for (int k = 0; k < 4; k++) {
                int d = abs(i - (j0 + k));
                v[k]  = s_lr[d] * invln;
                sg[k] = (int)s_segd[d];
            }
            float* a = out + (size_t)i * S + j0;
#pragma unroll
            for (int hh = 0; hh < H / 2; hh++) {
                float4 p0 = tab4[sg[0] * (HP / 2) + hh];
                float4 p1 = tab4[sg[1] * (HP / 2) + hh];
                float4 p2 = tab4[sg[2] * (HP / 2) + hh];
                float4 p3 = tab4[sg[3] * (HP / 2) + hh];
                float4 o0, o1;
                o0.x = fmaf(v[0], p0.x, p0.y);
                o0.y = fmaf(v[1], p1.x, p1.y);
                o0.z = fmaf(v[2], p2.x, p2.y);
                o0.w = fmaf(v[3], p3.x, p3.y);
                o1.x = fmaf(v[0], p0.z, p0.w);
                o1.y = fmaf(v[1], p1.z, p1.w);
                o1.z = fmaf(v[2], p2.z, p2.w);
                o1.w = fmaf(v[3], p3.z, p3.w);
                *reinterpret_cast<float4*>(a + (size_t)(2 * hh)     * SS) = o0;
                *reinterpret_cast<float4*>(a + (size_t)(2 * hh + 1) * SS) = o1;
            }
            if (H & 1) {
                float2 q0 = s_tab[sg[0] * HP + (H - 1)];
                float2 q1 = s_tab[sg[1] * HP + (H - 1)];
                float2 q2 = s_tab[sg[2] * HP + (H - 1)];
                float2 q3 = s_tab[sg[3] * HP + (H - 1)];
                float4 o;
                o.x = fmaf(v[0], q0.x, q0.y);
                o.y = fmaf(v[1], q1.x, q1.y);
                o.z = fmaf(v[2], q2.x, q2.y);
                o.w = fmaf(v[3], q3.x, q3.y);
                *reinterpret_cast<float4*>(a + (size_t)(H - 1) * SS) = o;
            }
        }

        // scalar tail (only if S % 4 != 0)
        int tail = S & ~3;
        for (int j = tail + t; j < S; j += blockDim.x) {
            int d = abs(i - j);
            float v = s_lr[d] * invln;
            int s = (int)s_segd[d];
            for (int h = 0; h < H; h++) {
                float2 ti = s_tab[s * HP + h];
                out[(size_t)h * SS + (size_t)i * S + j] = fmaf(v, ti.x, ti.y);
            }
        }
        __syncthreads();   // s_segd reused next row
    }
}

// generic-H fallback (same algorithm, runtime H)
__global__ void __launch_bounds__(256)
fire_main_gen(float* __restrict__ out, int S, int H) {
    int t = threadIdx.x;
    const int   nbp   = g_nbp;
    const float ndlo  = g_ndlo;
    const float scale = g_scale;
    const size_t SS   = (size_t)S * (size_t)S;

    for (int r = 0; r < ROWS_PER_BLOCK; r++) {
        int i = blockIdx.x * ROWS_PER_BLOCK + r;
        if (i >= S) break;
        const float invln = __ldg(&g_invln[i]);
        for (int j = t; j < S; j += blockDim.x) {
            int d = abs(i - j);
            float v = __ldg(&g_lr[d]) * invln;
            int kq = (int)((v - ndlo) * scale);
            kq = max(0, min(LUTN - 1, kq));
            int s = (int)(__ldg(&g_lut[kq]) & 0x7fu);
            while (s > 0 && v < __ldg(&g_bp[s - 1])) s--;
            while (s < nbp && v >= __ldg(&g_bp[s])) s++;
            for (int h = 0; h < H; h++) {
                float2 ti = __ldg(&g_tab[s * HP + h]);
                out[(size_t)h * SS + (size_t)i * S + j] = fmaf(v, ti.x, ti.y);
            }
        }
    }
}

extern "C" void kernel_launch(void* const* d_in, const int* in_sizes, int n_in,
                              void* d_out, int out_size) {
    // metadata order: x, w1, b1, w2, b2, c, L_multiplier, init_L
    const float* w1 = (const float*)d_in[1];
    const float* b1 = (const float*)d_in[2];
    const float* w2 = (const float*)d_in[3];
    const float* b2 = (const float*)d_in[4];
    const float* c  = (const float*)d_in[5];
    const float* Lm = (const float*)d_in[6];
    const float* iL = (const float*)d_in[7];

    int W = in_sizes[2];
    int H = in_sizes[4];
    long long SSll = (long long)out_size / (long long)H;
    int S = (int)(sqrt((double)SSll) + 0.5);

    fire_setup<<<64, 256>>>(w1, b1, w2, b2, c, Lm, iL, S, W, H);

    dim3 grid((S + ROWS_PER_BLOCK - 1) / ROWS_PER_BLOCK);
    if (H == 12)
        fire_main<12><<<grid, 256>>>((float*)d_out, S);
    else
        fire_main_gen<<<grid, 256>>>((float*)d_out, S, H);
}